// round 2
// baseline (speedup 1.0000x reference)
#include <cuda_runtime.h>
#include <math.h>

// Problem constants
#define B_  8
#define T_  2048
#define C_  512
#define U_  512
#define NG  1536          // 3*U
#define KK  1024          // 2*C (W=2 window)
#define MM  (B_ * T_)     // 16384 rows

// Scratch: activated gates, [M, U] each. __device__ globals (no runtime alloc).
__device__ float g_Z[(size_t)MM * U_];
__device__ float g_F[(size_t)MM * U_];
__device__ float g_O[(size_t)MM * U_];

// ---------------------------------------------------------------------------
// Kernel 1: fused causal-conv GEMM + bias + activation.
// gates[m][n] = sum_k A[m][k] * Kmat[k][n] + bias[n]
//   A[m][k] = x[(m-1)*512 + k]  (contiguous window), zero when (t==0 && k<512)
//   Kmat[k][n] = kernel[k*1536 + n]   (k = w*512 + c matches conv layout)
// Output region by n: [0,512) -> Z=tanh, [512,1024) -> F=sigmoid, [1024,1536) -> O=sigmoid
// Tile: BM=128, BN=128, BK=16, 256 threads, 8x8 per-thread, double-buffered SMEM.
// ---------------------------------------------------------------------------
#define BM 128
#define BN 128
#define BKT 16

__device__ __forceinline__ float sigmoidf_(float v) {
    return 1.0f / (1.0f + expf(-v));
}

__global__ __launch_bounds__(256) void gemm_gates_kernel(
    const float* __restrict__ x,
    const float* __restrict__ kern,
    const float* __restrict__ bias)
{
    __shared__ float As[2][BKT][BM];   // transposed: As[k][row]
    __shared__ float Bs[2][BKT][BN];

    const int tid = threadIdx.x;
    const int bn  = blockIdx.x;            // 0..11
    const int m0  = blockIdx.y * BM;       // row base
    const int n0  = bn * BN;

    const int tx = tid & 15;               // 0..15 (cols)
    const int ty = tid >> 4;               // 0..15 (rows)

    // A tile load mapping: 128 rows x 16 k -> 512 float4; thread loads 2.
    const int arow = tid >> 2;             // 0..63
    const int ac4  = (tid & 3) * 4;        // 0,4,8,12
    const int mA0  = m0 + arow;
    const int mA1  = m0 + arow + 64;

    // B tile load mapping: 16 k x 128 n -> 512 float4; thread loads 2.
    const int brow = tid >> 5;             // 0..7
    const int bc4  = (tid & 31) * 4;       // 0..124

    float acc[8][8];
    #pragma unroll
    for (int i = 0; i < 8; i++)
        #pragma unroll
        for (int j = 0; j < 8; j++) acc[i][j] = 0.0f;

    const int nK = KK / BKT;               // 64

    // ---- helpers (inlined manually) ----
    // preload tile 0
    {
        int kg = ac4;
        bool p0 = !(((mA0 & (T_ - 1)) == 0) && (kg < C_));
        bool p1 = !(((mA1 & (T_ - 1)) == 0) && (kg < C_));
        float4 r0 = p0 ? *(const float4*)(x + (mA0 - 1) * C_ + kg) : make_float4(0.f,0.f,0.f,0.f);
        float4 r1 = p1 ? *(const float4*)(x + (mA1 - 1) * C_ + kg) : make_float4(0.f,0.f,0.f,0.f);
        As[0][ac4 + 0][arow] = r0.x; As[0][ac4 + 1][arow] = r0.y;
        As[0][ac4 + 2][arow] = r0.z; As[0][ac4 + 3][arow] = r0.w;
        As[0][ac4 + 0][arow + 64] = r1.x; As[0][ac4 + 1][arow + 64] = r1.y;
        As[0][ac4 + 2][arow + 64] = r1.z; As[0][ac4 + 3][arow + 64] = r1.w;

        float4 q0 = *(const float4*)(kern + (size_t)(brow)     * NG + n0 + bc4);
        float4 q1 = *(const float4*)(kern + (size_t)(brow + 8) * NG + n0 + bc4);
        *(float4*)&Bs[0][brow][bc4]     = q0;
        *(float4*)&Bs[0][brow + 8][bc4] = q1;
    }
    __syncthreads();

    float4 a0n, a1n, b0n, b1n;

    for (int kt = 0; kt < nK; kt++) {
        const int cur = kt & 1;

        if (kt < nK - 1) {
            int kg = (kt + 1) * BKT + ac4;
            bool p0 = !(((mA0 & (T_ - 1)) == 0) && (kg < C_));
            bool p1 = !(((mA1 & (T_ - 1)) == 0) && (kg < C_));
            a0n = p0 ? *(const float4*)(x + (mA0 - 1) * C_ + kg) : make_float4(0.f,0.f,0.f,0.f);
            a1n = p1 ? *(const float4*)(x + (mA1 - 1) * C_ + kg) : make_float4(0.f,0.f,0.f,0.f);
            int kgb = (kt + 1) * BKT;
            b0n = *(const float4*)(kern + (size_t)(kgb + brow)     * NG + n0 + bc4);
            b1n = *(const float4*)(kern + (size_t)(kgb + brow + 8) * NG + n0 + bc4);
        }

        // compute on S[cur]
        #pragma unroll
        for (int kk = 0; kk < BKT; kk++) {
            float4 av0 = *(const float4*)&As[cur][kk][ty * 8];
            float4 av1 = *(const float4*)&As[cur][kk][ty * 8 + 4];
            float4 bv0 = *(const float4*)&Bs[cur][kk][tx * 8];
            float4 bv1 = *(const float4*)&Bs[cur][kk][tx * 8 + 4];
            float a[8] = {av0.x, av0.y, av0.z, av0.w, av1.x, av1.y, av1.z, av1.w};
            float b[8] = {bv0.x, bv0.y, bv0.z, bv0.w, bv1.x, bv1.y, bv1.z, bv1.w};
            #pragma unroll
            for (int i = 0; i < 8; i++)
                #pragma unroll
                for (int j = 0; j < 8; j++)
                    acc[i][j] = fmaf(a[i], b[j], acc[i][j]);
        }

        if (kt < nK - 1) {
            const int nxt = cur ^ 1;
            As[nxt][ac4 + 0][arow] = a0n.x; As[nxt][ac4 + 1][arow] = a0n.y;
            As[nxt][ac4 + 2][arow] = a0n.z; As[nxt][ac4 + 3][arow] = a0n.w;
            As[nxt][ac4 + 0][arow + 64] = a1n.x; As[nxt][ac4 + 1][arow + 64] = a1n.y;
            As[nxt][ac4 + 2][arow + 64] = a1n.z; As[nxt][ac4 + 3][arow + 64] = a1n.w;
            *(float4*)&Bs[nxt][brow][bc4]     = b0n;
            *(float4*)&Bs[nxt][brow + 8][bc4] = b1n;
        }
        __syncthreads();
    }

    // Epilogue: whole CTA lies in one gate region (BN=128 divides 512).
    const int gate = bn >> 2;              // 0:z 1:f 2:o
    float* dst = (gate == 0) ? g_Z : ((gate == 1) ? g_F : g_O);
    const int colbase = (bn & 3) * BN + tx * 8;

    float bv[8];
    #pragma unroll
    for (int j = 0; j < 8; j++) bv[j] = bias[n0 + tx * 8 + j];

    #pragma unroll
    for (int i = 0; i < 8; i++) {
        const int m = m0 + ty * 8 + i;
        float v[8];
        #pragma unroll
        for (int j = 0; j < 8; j++) {
            float g = acc[i][j] + bv[j];
            v[j] = (gate == 0) ? tanhf(g) : sigmoidf_(g);
        }
        float4* p = (float4*)(dst + (size_t)m * U_ + colbase);
        p[0] = make_float4(v[0], v[1], v[2], v[3]);
        p[1] = make_float4(v[4], v[5], v[6], v[7]);
    }
}

// ---------------------------------------------------------------------------
// Kernel 2: sequential fo-pool scan + output gate.
// One thread per (b,u) chain: h_t = f*h + (1-f)*z = fma(f, h - z, z); out = h*o.
// Loads coalesced across u (consecutive threads -> consecutive addresses).
// ---------------------------------------------------------------------------
__global__ __launch_bounds__(128) void scan_kernel(
    const float* __restrict__ init_state,
    float* __restrict__ out)
{
    const int id = blockIdx.x * blockDim.x + threadIdx.x;  // 0..4095
    const int b  = id >> 9;
    const int u  = id & (U_ - 1);

    float h = init_state[u];
    size_t base = (size_t)b * T_ * U_ + u;

    #pragma unroll 4
    for (int t = 0; t < T_; t++) {
        size_t idx = base + (size_t)t * U_;
        float f = g_F[idx];
        float z = g_Z[idx];
        float o = g_O[idx];
        h = fmaf(f, h - z, z);
        out[idx] = h * o;
    }
}

// ---------------------------------------------------------------------------
extern "C" void kernel_launch(void* const* d_in, const int* in_sizes, int n_in,
                              void* d_out, int out_size)
{
    const float* x    = (const float*)d_in[0];  // [8,2048,512]
    const float* kern = (const float*)d_in[1];  // [2,512,1536]
    const float* bias = (const float*)d_in[2];  // [1536]
    const float* init = (const float*)d_in[3];  // [1,512]
    float* out = (float*)d_out;                 // [8,2048,512]

    dim3 grid(NG / BN, MM / BM);                // (12, 128)
    gemm_gates_kernel<<<grid, 256>>>(x, kern, bias);
    scan_kernel<<<(B_ * U_) / 128, 128>>>(init, out);
}

// round 4
// speedup vs baseline: 3.9944x; 3.9944x over previous
#include <cuda_runtime.h>
#include <cuda_bf16.h>
#include <stdint.h>

// ---------------------------------------------------------------------------
// Problem constants
// ---------------------------------------------------------------------------
#define B_  8
#define T_  2048
#define C_  512
#define U_  512
#define NG  1536          // 3*U
#define KP  1024          // K per split (2*C, W=2 window)
#define MM  (B_ * T_)     // 16384
#define KTOT 3072         // 3 bf16 splits x 1024
#define NITER 96          // KTOT / BK

// GEMM tiling
#define BM 256
#define BN 128
#define BK 32             // bf16 per chunk
#define LDR 80            // padded smem row bytes (64 data + 16 pad)
#define A_STAGE (BM * LDR)          // 20480
#define B_STAGE (BN * LDR)          // 10240
#define STAGE_BYTES (A_STAGE + B_STAGE)   // 30720
#define DEPTH 3
#define SMEM_REQ (DEPTH * STAGE_BYTES)    // 92160

// scan chunking
#define NCH 32
#define CL  (T_ / NCH)    // 64

// ---------------------------------------------------------------------------
// Device scratch (static, no runtime alloc)
// ---------------------------------------------------------------------------
__device__ float g_Z[(size_t)MM * U_];
__device__ float g_F[(size_t)MM * U_];
__device__ float g_O[(size_t)MM * U_];
__device__ __nv_bfloat16 g_Xh[(size_t)MM * C_];
__device__ __nv_bfloat16 g_Xl[(size_t)MM * C_];
__device__ __nv_bfloat16 g_WhT[(size_t)NG * KP];
__device__ __nv_bfloat16 g_WlT[(size_t)NG * KP];
__device__ float g_cH[B_ * NCH * U_];
__device__ float g_cP[B_ * NCH * U_];
__device__ float g_Hin[B_ * NCH * U_];

// ---------------------------------------------------------------------------
// Helpers
// ---------------------------------------------------------------------------
__device__ __forceinline__ uint32_t smem_u32(const void* p) {
    uint32_t a;
    asm("{ .reg .u64 t; cvta.to.shared.u64 t, %1; cvt.u32.u64 %0, t; }"
        : "=r"(a) : "l"(p));
    return a;
}

#define CP16P(saddr, gptr, sz) \
    asm volatile("cp.async.cg.shared.global [%0], [%1], 16, %2;" \
                 :: "r"(saddr), "l"(gptr), "r"(sz))
#define CP_COMMIT() asm volatile("cp.async.commit_group;")
#define CP_WAIT1()  asm volatile("cp.async.wait_group 1;")

#define LDSM_X4(r0, r1, r2, r3, addr) \
    asm volatile("ldmatrix.sync.aligned.m8n8.x4.shared.b16 {%0,%1,%2,%3}, [%4];" \
                 : "=r"(r0), "=r"(r1), "=r"(r2), "=r"(r3) : "r"(addr))

#define MMA16816(d, a, b0, b1) \
    asm volatile("mma.sync.aligned.m16n8k16.row.col.f32.bf16.bf16.f32 " \
                 "{%0,%1,%2,%3}, {%4,%5,%6,%7}, {%8,%9}, {%0,%1,%2,%3};" \
                 : "+f"((d)[0]), "+f"((d)[1]), "+f"((d)[2]), "+f"((d)[3]) \
                 : "r"((a)[0]), "r"((a)[1]), "r"((a)[2]), "r"((a)[3]), \
                   "r"(b0), "r"(b1))

__device__ __forceinline__ float tanh_fast(float x) {
    float r; asm("tanh.approx.f32 %0, %1;" : "=f"(r) : "f"(x)); return r;
}
__device__ __forceinline__ float sig_fast(float x) {
    float e; asm("ex2.approx.f32 %0, %1;" : "=f"(e) : "f"(-x * 1.4426950408889634f));
    float r; asm("rcp.approx.f32 %0, %1;" : "=f"(r) : "f"(1.0f + e)); return r;
}

// ---------------------------------------------------------------------------
// prep_x: split fp32 x into bf16 hi + bf16 residual lo (elementwise)
// ---------------------------------------------------------------------------
__global__ __launch_bounds__(256) void prep_x(const float* __restrict__ x) {
    size_t g = (size_t)blockIdx.x * 256 + threadIdx.x;   // MM*C/4 threads
    float4 v = ((const float4*)x)[g];
    __nv_bfloat16 h0 = __float2bfloat16(v.x);
    __nv_bfloat16 h1 = __float2bfloat16(v.y);
    __nv_bfloat16 h2 = __float2bfloat16(v.z);
    __nv_bfloat16 h3 = __float2bfloat16(v.w);
    __nv_bfloat162 ha; ha.x = h0; ha.y = h1;
    __nv_bfloat162 hb; hb.x = h2; hb.y = h3;
    __nv_bfloat162 la; la.x = __float2bfloat16(v.x - __bfloat162float(h0));
    la.y = __float2bfloat16(v.y - __bfloat162float(h1));
    __nv_bfloat162 lb; lb.x = __float2bfloat16(v.z - __bfloat162float(h2));
    lb.y = __float2bfloat16(v.w - __bfloat162float(h3));
    ((__nv_bfloat162*)g_Xh)[g * 2]     = ha;
    ((__nv_bfloat162*)g_Xh)[g * 2 + 1] = hb;
    ((__nv_bfloat162*)g_Xl)[g * 2]     = la;
    ((__nv_bfloat162*)g_Xl)[g * 2 + 1] = lb;
}

// prep_w: transpose + split kernel[k,n] -> WhT/WlT[n,k]
__global__ void prep_w(const float* __restrict__ kern) {
    __shared__ __nv_bfloat16 sh[32][33];
    __shared__ __nv_bfloat16 sl[32][33];
    int k = blockIdx.y * 32 + threadIdx.y;
    int n = blockIdx.x * 32 + threadIdx.x;
    float v = kern[(size_t)k * NG + n];
    __nv_bfloat16 hi = __float2bfloat16(v);
    sh[threadIdx.y][threadIdx.x] = hi;
    sl[threadIdx.y][threadIdx.x] = __float2bfloat16(v - __bfloat162float(hi));
    __syncthreads();
    int nn = blockIdx.x * 32 + threadIdx.y;
    int kk = blockIdx.y * 32 + threadIdx.x;
    g_WhT[(size_t)nn * KP + kk] = sh[threadIdx.x][threadIdx.y];
    g_WlT[(size_t)nn * KP + kk] = sl[threadIdx.x][threadIdx.y];
}

// ---------------------------------------------------------------------------
// GEMM: gates[16384, 1536] = A[16384, 3072] @ Wcat[3072, 1536] via mma.sync
// A row m, split s, k: source Xs[m + w - 1, c]  (w=k/512, c=k%512),
// zero row when (w==0 && m%2048==0). Fused bias + activation epilogue.
// ---------------------------------------------------------------------------
__global__ __launch_bounds__(512) void mma_gates(const float* __restrict__ bias) {
    extern __shared__ char smem[];
    const uint32_t sbase = smem_u32(smem);

    const int tid = threadIdx.x;
    const int wid = tid >> 5;
    const int lane = tid & 31;
    const int n0 = blockIdx.x * BN;
    const int m0 = blockIdx.y * BM;

    const int wm = (wid & 7) * 32;      // warp m offset (8 warps along M)
    const int wn = (wid >> 3) * 64;     // warp n offset (2 warps along N)

    const __nv_bfloat16* const Asrc[3] = { g_Xh, g_Xh, g_Xl };
    const __nv_bfloat16* const Bsrc[3] = { g_WhT, g_WlT, g_WhT };

    // cp.async chunk assignment: 1536 16B-chunks per stage, 3 per thread.
    //  i=0: A rows 0..127, i=1: A rows 128..255, i=2: B rows 0..127
    const int rowq = tid >> 2;          // 0..127
    const int jq   = tid & 3;           // chunk-in-row

#define LOAD_STAGE(cc) do { \
    const int _c = (cc); \
    const int _s = _c >> 5; \
    const int _kb = (_c & 31) * BK; \
    const __nv_bfloat16* _Ap = Asrc[_s]; \
    const __nv_bfloat16* _Bp = Bsrc[_s]; \
    const uint32_t _st = sbase + (uint32_t)(_c % DEPTH) * STAGE_BYTES; \
    _Pragma("unroll") \
    for (int _i = 0; _i < 2; _i++) { \
        int _row = rowq + _i * 128; \
        int _m = m0 + _row; \
        int _k = _kb + jq * 8; \
        int _w = _k >> 9; \
        int _cc2 = _k & 511; \
        int _r = _m + _w - 1; \
        uint32_t _sz = (_w == 0 && (_m & (T_ - 1)) == 0) ? 0u : 16u; \
        if (_sz == 0u) _r = _m; \
        const void* _gp = _Ap + (size_t)_r * C_ + _cc2; \
        CP16P(_st + (uint32_t)(_row * LDR + jq * 16), _gp, _sz); \
    } \
    { \
        int _n = n0 + rowq; \
        const void* _gp = _Bp + (size_t)_n * KP + _kb + jq * 8; \
        CP16P(_st + (uint32_t)(A_STAGE + rowq * LDR + jq * 16), _gp, 16u); \
    } \
    CP_COMMIT(); \
} while (0)

    float acc[2][8][4];
#pragma unroll
    for (int mt = 0; mt < 2; mt++)
#pragma unroll
        for (int nt = 0; nt < 8; nt++)
#pragma unroll
            for (int r = 0; r < 4; r++) acc[mt][nt][r] = 0.0f;

    LOAD_STAGE(0);
    LOAD_STAGE(1);

    // ldmatrix lane address components (fixed per thread)
    const int a_row = lane & 15;             // row within m16 tile
    const int a_chk = lane >> 4;             // 0/1 -> k half
    const int b_row = (lane & 7) + ((lane >> 4) << 3);  // n row within pair
    const int b_chk = (lane >> 3) & 1;       // k half select

#pragma unroll 1
    for (int cc = 0; cc < NITER; cc++) {
        CP_WAIT1();
        __syncthreads();
        if (cc + 2 < NITER) {
            LOAD_STAGE(cc + 2);
        } else {
            CP_COMMIT();
        }

        const uint32_t st = sbase + (uint32_t)(cc % DEPTH) * STAGE_BYTES;
        const uint32_t sA = st + (uint32_t)((wm + a_row) * LDR);
        const uint32_t sB = st + (uint32_t)(A_STAGE + (wn + b_row) * LDR);

#pragma unroll
        for (int ks = 0; ks < 2; ks++) {
            uint32_t a[2][4];
            uint32_t b[4][4];
#pragma unroll
            for (int mt = 0; mt < 2; mt++) {
                uint32_t ad = sA + (uint32_t)(mt * 16 * LDR + (a_chk + ks * 2) * 16);
                LDSM_X4(a[mt][0], a[mt][1], a[mt][2], a[mt][3], ad);
            }
#pragma unroll
            for (int p = 0; p < 4; p++) {
                uint32_t bd = sB + (uint32_t)(p * 16 * LDR + (b_chk + ks * 2) * 16);
                LDSM_X4(b[p][0], b[p][1], b[p][2], b[p][3], bd);
            }
#pragma unroll
            for (int mt = 0; mt < 2; mt++)
#pragma unroll
                for (int p = 0; p < 4; p++) {
                    MMA16816(acc[mt][2 * p],     a[mt], b[p][0], b[p][1]);
                    MMA16816(acc[mt][2 * p + 1], a[mt], b[p][2], b[p][3]);
                }
        }
    }

    // ---- epilogue: bias + activation + store, straight from registers ----
    const int ng = n0 + wn;                   // warp n base (global)
    const int gate = ng >> 9;                 // 0:z 1:f 2:o
    float* dst = (gate == 0) ? g_Z : ((gate == 1) ? g_F : g_O);
    const int colw = (ng & 511) + (lane & 3) * 2;   // thread col base in gate

    float bs0[8], bs1[8];
#pragma unroll
    for (int nt = 0; nt < 8; nt++) {
        bs0[nt] = __ldg(bias + ng + (lane & 3) * 2 + nt * 8);
        bs1[nt] = __ldg(bias + ng + (lane & 3) * 2 + nt * 8 + 1);
    }

#pragma unroll
    for (int mt = 0; mt < 2; mt++) {
        int row = m0 + wm + mt * 16 + (lane >> 2);
        float* p0 = dst + (size_t)row * U_;
        float* p1 = dst + (size_t)(row + 8) * U_;
#pragma unroll
        for (int nt = 0; nt < 8; nt++) {
            int col = colw + nt * 8;
            float g0 = acc[mt][nt][0] + bs0[nt];
            float g1 = acc[mt][nt][1] + bs1[nt];
            float g2 = acc[mt][nt][2] + bs0[nt];
            float g3 = acc[mt][nt][3] + bs1[nt];
            float2 v0, v1;
            if (gate == 0) {
                v0.x = tanh_fast(g0); v0.y = tanh_fast(g1);
                v1.x = tanh_fast(g2); v1.y = tanh_fast(g3);
            } else {
                v0.x = sig_fast(g0); v0.y = sig_fast(g1);
                v1.x = sig_fast(g2); v1.y = sig_fast(g3);
            }
            *(float2*)(p0 + col) = v0;
            *(float2*)(p1 + col) = v1;
        }
    }
}

// ---------------------------------------------------------------------------
// Chunked fo-pool scan (h affine in h_in: h = P*h_in + H)
// ---------------------------------------------------------------------------
__global__ __launch_bounds__(256) void scan_pass1() {
    int id = blockIdx.x * 256 + threadIdx.x;       // B*NCH*U = 131072
    int u = id & 511;
    int ch = (id >> 9) & (NCH - 1);
    int b = id >> 14;
    size_t base = ((size_t)b * T_ + (size_t)ch * CL) * U_ + u;
    float h = 0.0f, P = 1.0f;
#pragma unroll 8
    for (int t = 0; t < CL; t++) {
        float f = g_F[base + (size_t)t * U_];
        float z = g_Z[base + (size_t)t * U_];
        h = fmaf(f, h - z, z);
        P *= f;
    }
    int o = (b * NCH + ch) * U_ + u;
    g_cH[o] = h;
    g_cP[o] = P;
}

__global__ __launch_bounds__(512) void scan_pass2(const float* __restrict__ init) {
    int id = blockIdx.x * 512 + threadIdx.x;       // 4096 = B*U
    int u = id & 511;
    int b = id >> 9;
    float h = init[u];
#pragma unroll
    for (int c = 0; c < NCH; c++) {
        int o = (b * NCH + c) * U_ + u;
        g_Hin[o] = h;
        h = fmaf(g_cP[o], h, g_cH[o]);
    }
}

__global__ __launch_bounds__(256) void scan_pass3(float* __restrict__ out) {
    int id = blockIdx.x * 256 + threadIdx.x;
    int u = id & 511;
    int ch = (id >> 9) & (NCH - 1);
    int b = id >> 14;
    size_t base = ((size_t)b * T_ + (size_t)ch * CL) * U_ + u;
    float h = g_Hin[(b * NCH + ch) * U_ + u];
#pragma unroll 8
    for (int t = 0; t < CL; t++) {
        size_t idx = base + (size_t)t * U_;
        float f = g_F[idx];
        float z = g_Z[idx];
        float o = g_O[idx];
        h = fmaf(f, h - z, z);
        out[idx] = h * o;
    }
}

// ---------------------------------------------------------------------------
extern "C" void kernel_launch(void* const* d_in, const int* in_sizes, int n_in,
                              void* d_out, int out_size)
{
    const float* x    = (const float*)d_in[0];  // [8,2048,512]
    const float* kern = (const float*)d_in[1];  // [2,512,1536]
    const float* bias = (const float*)d_in[2];  // [1536]
    const float* init = (const float*)d_in[3];  // [1,512]
    float* out = (float*)d_out;                 // [8,2048,512]

    cudaFuncSetAttribute(mma_gates, cudaFuncAttributeMaxDynamicSharedMemorySize, SMEM_REQ);

    prep_x<<<(MM * C_) / (256 * 4), 256>>>(x);
    prep_w<<<dim3(NG / 32, KP / 32), dim3(32, 32)>>>(kern);
    mma_gates<<<dim3(NG / BN, MM / BM), 512, SMEM_REQ>>>(bias);
    scan_pass1<<<(B_ * NCH * U_) / 256, 256>>>();
    scan_pass2<<<(B_ * U_) / 512, 512>>>(init);
    scan_pass3<<<(B_ * NCH * U_) / 256, 256>>>(out);
}